// round 5
// baseline (speedup 1.0000x reference)
#include <cuda_runtime.h>
#include <cuda_bf16.h>

#define NBX 512
#define NBY 512
#define KK  5
#define TARGET_AREA 0.9f
#define NC (NBX * NBY)          // bucket key space (stride 512)
#define CAP 16
#define OVF_CAP (1 << 18)

#define GRID_F 296              // 2 CTAs/SM x 148 SMs — all resident (guaranteed by launch_bounds)
#define TPB    256

// ---- static device scratch (no runtime allocation allowed) ----
__device__ __align__(16) float g_scratch[NC];          // deposits only; zeroed by finish
__device__ int    g_cnt[NC];                           // zeroed by merge after read
__device__ float4 g_rec[CAP * NC];                     // slot-major records
__device__ float4 g_ovf[OVF_CAP];
__device__ int    g_ovf_cnt;                           // reset by finish
__device__ int    g_bar;                               // grid barrier; reset by finish
__device__ float  g_sum;                               // reset by finish
__device__ int    g_done;                              // reset by finish

// ---------------- packed f32x2 helpers (sm_103a FFMA2) ----------------
__device__ __forceinline__ unsigned long long pk2(float lo, float hi) {
    unsigned long long r;
    asm("mov.b64 %0, {%1, %2};" : "=l"(r) : "f"(lo), "f"(hi));
    return r;
}
__device__ __forceinline__ void upk2(unsigned long long v, float& lo, float& hi) {
    asm("mov.b64 {%0, %1}, %2;" : "=f"(lo), "=f"(hi) : "l"(v));
}
__device__ __forceinline__ unsigned long long fma2(unsigned long long a,
                                                   unsigned long long b,
                                                   unsigned long long c) {
    unsigned long long r;
    asm("fma.rn.f32x2 %0, %1, %2, %3;" : "=l"(r) : "l"(a), "l"(b), "l"(c));
    return r;
}

// Vectorized fp32 reduction (no return)
__device__ __forceinline__ void red_add_v4(float* addr, float a, float b, float c, float d) {
    asm volatile("red.global.add.v4.f32 [%0], {%1, %2, %3, %4};"
                 :: "l"(addr), "f"(a), "f"(b), "f"(c), "f"(d) : "memory");
}

// x flavor: 5 window potentials starting at s0
__device__ __forceinline__ void pot_x5(float coord, float s, int s0, float* p) {
    float ctr = coord + 0.5f * s;
    float a = 4.0f / ((s + 2.0f) * (s + 4.0f));
    float c = s;
    float cb = c * (2.0f / (s + 4.0f));
    float p1 = 0.5f * s + 1.0f;
    float p2 = 0.5f * s + 2.0f;
#pragma unroll
    for (int k = 0; k < KK; k++) {
        float d = fabsf(ctr - ((float)(s0 + k) + 0.5f));
        float v;
        if (d < p1)      v = c * (1.0f - a * d * d);
        else if (d < p2) { float t = d - p2; v = cb * t * t; }
        else             v = 0.0f;
        p[k] = v;
    }
}

// y flavor: 8 padded lanes from aligned ybase, masked to [sy0, sy0+5)
__device__ __forceinline__ void pot_y8(float coord, float s, int sy0, int ybase, float* p) {
    float ctr = coord + 0.5f * s;
    float a = 4.0f / ((s + 2.0f) * (s + 4.0f));
    float c = s;
    float cb = c * (2.0f / (s + 4.0f));
    float p1 = 0.5f * s + 1.0f;
    float p2 = 0.5f * s + 2.0f;
#pragma unroll
    for (int j = 0; j < 8; j++) {
        int g = ybase + j;
        float d = fabsf(ctr - ((float)g + 0.5f));
        float v;
        if (d < p1)      v = c * (1.0f - a * d * d);
        else if (d < p2) { float t = d - p2; v = cb * t * t; }
        else             v = 0.0f;
        bool in = (g >= sy0) && (g < sy0 + KK);
        p[j] = in ? v : 0.0f;
    }
}

// ---------------------------------------------------------------------------
// Fused kernel: bucket -> grid barrier -> merge (+overflow)
// All 296 blocks are resident (2/SM, regs capped at 128, smem 0) so the
// software barrier cannot deadlock.
// ---------------------------------------------------------------------------
__global__ void __launch_bounds__(TPB, 2) fused_kernel(
    const float* __restrict__ pos,
    const float* __restrict__ sxs,
    const float* __restrict__ sys,
    int n)
{
    const int gtid   = blockIdx.x * TPB + threadIdx.x;
    const int stride = GRID_F * TPB;

    // ===== Phase A: bucket nodes by unclamped cell key =====
    for (int i = gtid; i < n; i += stride) {
        float x  = pos[i];
        float y  = pos[n + i];
        float sx = sxs[i];
        float sy = sys[i];
        int kx = (int)floorf(x - 2.0f) + 2;   // [0, 510]
        int ky = (int)floorf(y - 2.0f) + 2;
        int c = (kx << 9) + ky;

        int slot = atomicAdd(&g_cnt[c], 1);
        float4 r = make_float4(x, y, sx, sy);
        if (slot < CAP) {
            g_rec[slot * NC + c] = r;
        } else {
            int o = atomicAdd(&g_ovf_cnt, 1);
            if (o < OVF_CAP) g_ovf[o] = r;
        }
    }

    // ===== Grid barrier =====
    __threadfence();
    __syncthreads();
    if (threadIdx.x == 0) {
        atomicAdd(&g_bar, 1);
        while (atomicAdd(&g_bar, 0) < GRID_F) { __nanosleep(128); }
    }
    __syncthreads();

    // ===== Phase B: merge buckets, deposit once per cell =====
    for (int c = gtid; c < NC; c += stride) {
        int cnt = g_cnt[c];
        if (cnt == 0) continue;
        g_cnt[c] = 0;                       // self-reset for next replay
        cnt = min(cnt, CAP);

        int kx = c >> 9;
        int ky = c & 511;
        int sx0 = min(max(kx - 2, 0), NBX - KK);
        int sy0 = min(max(ky - 2, 0), NBY - KK);
        int ybase = sy0 & ~3;

        unsigned long long acc[KK][4];
        unsigned long long z2 = pk2(0.0f, 0.0f);
#pragma unroll
        for (int a = 0; a < KK; a++)
#pragma unroll
            for (int j = 0; j < 4; j++) acc[a][j] = z2;

        for (int s = 0; s < cnt; s++) {
            float4 r = g_rec[s * NC + c];
            float px[KK], py[8];
            pot_x5(r.x, r.z, sx0, px);
            pot_y8(r.y, r.w, sy0, ybase, py);
            unsigned long long py2[4];
            py2[0] = pk2(py[0], py[1]);
            py2[1] = pk2(py[2], py[3]);
            py2[2] = pk2(py[4], py[5]);
            py2[3] = pk2(py[6], py[7]);
#pragma unroll
            for (int a = 0; a < KK; a++) {
                unsigned long long vx2 = pk2(px[a], px[a]);
#pragma unroll
                for (int j = 0; j < 4; j++)
                    acc[a][j] = fma2(vx2, py2[j], acc[a][j]);
            }
        }

        float* base = &g_scratch[sx0 * NBY + ybase];
#pragma unroll
        for (int a = 0; a < KK; a++) {
            float q0, q1, q2, q3, q4, q5, q6, q7;
            upk2(acc[a][0], q0, q1);
            upk2(acc[a][1], q2, q3);
            upk2(acc[a][2], q4, q5);
            upk2(acc[a][3], q6, q7);
            float* b = base + a * NBY;
            if (q0 != 0.0f || q1 != 0.0f || q2 != 0.0f || q3 != 0.0f)
                red_add_v4(b, q0, q1, q2, q3);
            if (q4 != 0.0f || q5 != 0.0f || q6 != 0.0f || q7 != 0.0f)
                red_add_v4(b + 4, q4, q5, q6, q7);
        }
    }

    // ===== Overflow fallback (empty in expectation) =====
    int total = min(g_ovf_cnt, OVF_CAP);
    for (int i = gtid; i < total; i += stride) {
        float4 r = g_ovf[i];
        int sx0 = min(max((int)floorf(r.x - 2.0f), 0), NBX - KK);
        int sy0 = min(max((int)floorf(r.y - 2.0f), 0), NBY - KK);
        int ybase = sy0 & ~3;
        float px[KK], py[8];
        pot_x5(r.x, r.z, sx0, px);
        pot_y8(r.y, r.w, sy0, ybase, py);
        float* base = &g_scratch[sx0 * NBY + ybase];
#pragma unroll
        for (int a = 0; a < KK; a++) {
            float vx = px[a];
            if (vx != 0.0f) {
                float* b = base + a * NBY;
                red_add_v4(b,     vx * py[0], vx * py[1], vx * py[2], vx * py[3]);
                red_add_v4(b + 4, vx * py[4], vx * py[5], vx * py[6], vx * py[7]);
            }
        }
    }
}

// ---------------------------------------------------------------------------
// Finish kernel: cost = sum((initial + scratch - target)^2); zero scratch
// behind itself; last block (ticket) writes out and resets all state.
// ---------------------------------------------------------------------------
__global__ void __launch_bounds__(256) finish_kernel(
    const float4* __restrict__ initial,
    float* __restrict__ out)
{
    int i = blockIdx.x * blockDim.x + threadIdx.x;    // 65536 threads = NC/4
    float acc = 0.0f;
    if (i < NC / 4) {
        float4 s  = ((float4*)g_scratch)[i];
        float4 d0 = initial[i];
        ((float4*)g_scratch)[i] = make_float4(0.f, 0.f, 0.f, 0.f);
        float a0 = s.x + d0.x - TARGET_AREA;
        float a1 = s.y + d0.y - TARGET_AREA;
        float a2 = s.z + d0.z - TARGET_AREA;
        float a3 = s.w + d0.w - TARGET_AREA;
        acc = a0 * a0 + a1 * a1 + a2 * a2 + a3 * a3;
    }

    __shared__ float sdata[8];
    int tid = threadIdx.x;
#pragma unroll
    for (int off = 16; off > 0; off >>= 1)
        acc += __shfl_xor_sync(0xFFFFFFFF, acc, off);
    if ((tid & 31) == 0) sdata[tid >> 5] = acc;
    __syncthreads();
    if (tid < 8) {
        float v = sdata[tid];
#pragma unroll
        for (int off = 4; off > 0; off >>= 1)
            v += __shfl_xor_sync(0xFF, v, off);
        if (tid == 0) {
            atomicAdd(&g_sum, v);
            __threadfence();
            int ticket = atomicAdd(&g_done, 1);
            if (ticket == (int)gridDim.x - 1) {
                out[0] = g_sum;
                g_sum = 0.0f;      // reset all state for next graph replay
                g_done = 0;
                g_bar = 0;
                g_ovf_cnt = 0;
            }
        }
    }
}

// ---------------------------------------------------------------------------
extern "C" void kernel_launch(void* const* d_in, const int* in_sizes, int n_in,
                              void* d_out, int out_size) {
    const float* pos = (const float*)d_in[0];
    const float* sx  = (const float*)d_in[1];
    const float* sy  = (const float*)d_in[2];
    // d_in[3..8]: ax..cy — recomputed analytically; d_in[9..10]: bin centers — analytic
    const float* initial = (const float*)d_in[11];
    float* out = (float*)d_out;

    int n = in_sizes[1];

    fused_kernel<<<GRID_F, TPB>>>(pos, sx, sy, n);
    finish_kernel<<<NC / 4 / 256, 256>>>((const float4*)initial, out);
}